// round 3
// baseline (speedup 1.0000x reference)
#include <cuda_runtime.h>
#include <math.h>
#include <float.h>

static constexpr int S = 1024;
static constexpr int Bd = 2;
static constexpr int D = 1024;
static constexpr int H = 16;
static constexpr int DEPTH = 64;
static constexpr int DFF = 4096;
static constexpr int R = S * Bd;      // 2048 token rows
static constexpr int BH = Bd * H;     // 32
static constexpr float SCALE = 0.125f; // 1/sqrt(64)
static constexpr float NEGV = -1000000000.0f;
static constexpr float EPSV = 1e-5f;

// ------------------- scratch (static device globals; no runtime alloc) -----
__device__ float g_Yv[R * D];        // V = X @ Wv   (flat rows)
__device__ float g_attn[R * D];      // attention output, flat == (S,B,D)
__device__ float g_h1[R * D];
__device__ float g_mid[R * DFF];
__device__ float g_ffn[R * D];
__device__ float g_wqsum[D * H];
__device__ float g_wksum[D * H];
__device__ float g_qsT[BH * S];      // scaled qs, [bh][s]
__device__ float g_ktsT[BH * S];     // kts (unscaled), [bh][s]
__device__ float g_A2[BH * S];
__device__ float g_P1[BH * S];
__device__ float g_SA1[BH];
__device__ float g_mx[BH];
__device__ float g_mn[BH];
__device__ float g_mx2[BH];
__device__ float g_mn2[BH];
__device__ int   g_kmx[BH];
__device__ int   g_kmn[BH];

// ------------------- K0: column-group sums of Wq, Wk -----------------------
__global__ void k_wsum(const float* __restrict__ wq, const float* __restrict__ wk) {
    int idx = blockIdx.x * blockDim.x + threadIdx.x;   // over D*H
    if (idx >= D * H) return;
    int k = idx / H, h = idx % H;
    const float* p1 = wq + (size_t)k * D + h * DEPTH;
    const float* p2 = wk + (size_t)k * D + h * DEPTH;
    float s1 = 0.f, s2 = 0.f;
#pragma unroll 16
    for (int d = 0; d < DEPTH; d++) { s1 += p1[d]; s2 += p2[d]; }
    g_wqsum[k * H + h] = s1;
    g_wksum[k * H + h] = s2;
}

// ------------------- K1: qs / kts = X @ Wsum (2048 x 16) -------------------
__global__ void k_qskts(const float* __restrict__ x) {
    int r = blockIdx.x;          // flat row of x (S,B,D) -> reshape row b'=r>>10
    int t = threadIdx.x;         // 256
    int h = t & 15, part = t >> 4;   // 16 parts
    float a1 = 0.f, a2 = 0.f;
    const float* xr = x + (size_t)r * D;
    for (int k = part; k < D; k += 16) {
        float xv = xr[k];
        a1 += xv * g_wqsum[k * H + h];
        a2 += xv * g_wksum[k * H + h];
    }
    __shared__ float s1[16][16];
    __shared__ float s2[16][16];
    s1[part][h] = a1; s2[part][h] = a2;
    __syncthreads();
    if (t < H) {
        float q = 0.f, kk = 0.f;
#pragma unroll
        for (int p = 0; p < 16; p++) { q += s1[p][t]; kk += s2[p][t]; }
        int b = r >> 10, s = r & 1023;   // raw-reshape coordinates
        g_qsT[(b * H + t) * S + s]  = SCALE * q;
        g_ktsT[(b * H + t) * S + s] = kk;
    }
}

// ------------------- SGEMM: C(M,N) = A(M,K) @ B(K,N) [+bias][+relu] --------
template <int EPI>   // 0: none, 1: bias+relu, 2: bias
__global__ void __launch_bounds__(256, 2)
k_sgemm(const float* __restrict__ A, const float* __restrict__ Bm,
        const float* __restrict__ bias, float* __restrict__ C,
        int M, int N, int K) {
    constexpr int BM = 128, BN = 128, BK = 8, TM = 8, TN = 8;
    __shared__ float As[BK][BM];
    __shared__ float Bs[BK][BN];
    int t = threadIdx.x;
    int tx = (t % 16) * TN;
    int ty = (t / 16) * TM;
    int arow = t >> 1, acol = (t & 1) * 4;
    int brow = t >> 5, bcol = (t & 31) * 4;
    const float* Ag = A + (size_t)(blockIdx.y * BM + arow) * K + acol;
    const float* Bg = Bm + (size_t)brow * N + blockIdx.x * BN + bcol;
    float acc[TM][TN] = {};
    float ar[TM], br[TN];
    for (int k0 = 0; k0 < K; k0 += BK) {
        float4 av = *(const float4*)Ag;
        float4 bv = *(const float4*)Bg;
        Ag += BK; Bg += (size_t)BK * N;
        As[acol + 0][arow] = av.x;
        As[acol + 1][arow] = av.y;
        As[acol + 2][arow] = av.z;
        As[acol + 3][arow] = av.w;
        *(float4*)(&Bs[brow][bcol]) = bv;
        __syncthreads();
#pragma unroll
        for (int kk = 0; kk < BK; kk++) {
            *(float4*)(ar)     = *(const float4*)(&As[kk][ty]);
            *(float4*)(ar + 4) = *(const float4*)(&As[kk][ty + 4]);
            *(float4*)(br)     = *(const float4*)(&Bs[kk][tx]);
            *(float4*)(br + 4) = *(const float4*)(&Bs[kk][tx + 4]);
#pragma unroll
            for (int i = 0; i < TM; i++)
#pragma unroll
                for (int j = 0; j < TN; j++)
                    acc[i][j] = fmaf(ar[i], br[j], acc[i][j]);
        }
        __syncthreads();
    }
    int crow = blockIdx.y * BM + ty;
    int ccol = blockIdx.x * BN + tx;
#pragma unroll
    for (int i = 0; i < TM; i++) {
        float out8[TN];
#pragma unroll
        for (int j = 0; j < TN; j++) {
            float v = acc[i][j];
            if constexpr (EPI >= 1) v += bias[ccol + j];
            if constexpr (EPI == 1) v = fmaxf(v, 0.f);
            out8[j] = v;
        }
        float* cp = C + (size_t)(crow + i) * N + ccol;
        *(float4*)(cp)     = *(float4*)(out8);
        *(float4*)(cp + 4) = *(float4*)(out8 + 4);
    }
}

// ------------------- K3: rel_w weighted reductions --------------------------
// A2[bh][k] = sum_{m<=k} (kts[m] + NEG*min(m,64)) * rel_w[bh][k][1023+m-k]
// P1[bh][k] = sum_{m<=k}  kts[m]                  * rel_w[bh][k][1023+m-k]
__global__ void k_relw(const float* __restrict__ rel) {
    int k = blockIdx.x;       // 0..1023
    int bh = blockIdx.y;      // 0..31
    int t = threadIdx.x;      // 256
    const float* row = rel + ((size_t)bh * S + k) * S;
    const float* kts = g_ktsT + bh * S;
    float a1 = 0.f, a2 = 0.f;
    for (int m = t; m <= k; m += 256) {
        float rv  = row[1023 - k + m];
        float kv  = kts[m];
        float ktm = kv + NEGV * (float)min(m, 64);
        a1 += kv * rv;
        a2 += ktm * rv;
    }
    __shared__ float s1[256];
    __shared__ float s2[256];
    s1[t] = a1; s2[t] = a2;
    __syncthreads();
    for (int o = 128; o > 0; o >>= 1) {
        if (t < o) { s1[t] += s1[t + o]; s2[t] += s2[t + o]; }
        __syncthreads();
    }
    if (t == 0) {
        g_P1[bh * S + k] = s1[0];
        g_A2[bh * S + k] = s2[0];
    }
}

// ------------------- K4: SA1 + top-2 max/min (with argidx) per bh -----------
__global__ void k_finalize() {
    int bh = blockIdx.x, t = threadIdx.x;   // 256
    __shared__ float ss[256];
    __shared__ float sv[256];
    __shared__ int   si[256];
    __shared__ float sw[256];
    __shared__ int   sj[256];
    const float* A2 = g_A2 + bh * S;
    float sa = 0.f, mx = -FLT_MAX, mn = FLT_MAX;
    int im = 0, imn = 0;
    for (int k = t; k < S; k += 256) {
        sa += g_P1[bh * S + k];
        float a = A2[k];
        if (a > mx) { mx = a; im = k; }
        if (a < mn) { mn = a; imn = k; }
    }
    ss[t] = sa; sv[t] = mx; si[t] = im; sw[t] = mn; sj[t] = imn;
    __syncthreads();
    for (int o = 128; o > 0; o >>= 1) {
        if (t < o) {
            ss[t] += ss[t + o];
            if (sv[t + o] > sv[t]) { sv[t] = sv[t + o]; si[t] = si[t + o]; }
            if (sw[t + o] < sw[t]) { sw[t] = sw[t + o]; sj[t] = sj[t + o]; }
        }
        __syncthreads();
    }
    int kmx = si[0], kmn = sj[0];
    float vmx = sv[0], vmn = sw[0], vsa = ss[0];
    __syncthreads();
    // second extremes (excluding the arg indices)
    float mx2 = -FLT_MAX, mn2 = FLT_MAX;
    for (int k = t; k < S; k += 256) {
        float a = A2[k];
        if (k != kmx && a > mx2) mx2 = a;
        if (k != kmn && a < mn2) mn2 = a;
    }
    sv[t] = mx2; sw[t] = mn2;
    __syncthreads();
    for (int o = 128; o > 0; o >>= 1) {
        if (t < o) { sv[t] = fmaxf(sv[t], sv[t + o]); sw[t] = fminf(sw[t], sw[t + o]); }
        __syncthreads();
    }
    if (t == 0) {
        g_SA1[bh] = vsa;
        g_mx[bh] = vmx; g_mn[bh] = vmn;
        g_mx2[bh] = sv[0]; g_mn2[bh] = sw[0];
        g_kmx[bh] = kmx; g_kmn[bh] = kmn;
    }
}

// ------------------- K5: one-hot gather (with exact softmax fallback) -------
// logits row j = cj * A2[:], cj = SCALE*qs[j]*SA1. If the top gap exceeds 90/|cj|
// the softmax is exactly one-hot in fp32 -> copy the winning V row.
__global__ void __launch_bounds__(256) k_attn2() {
    int bh = blockIdx.y;
    int b = bh >> 4, h = bh & 15;
    int t = threadIdx.x;
    int rg = t >> 4;          // 16 rows per block
    int lane = t & 15;        // 16 lanes -> 64 cols (float4 each)
    int j = blockIdx.x * 16 + rg;

    float cj = SCALE * g_qsT[bh * S + j] * g_SA1[bh];
    const float* Vb = g_Yv + (size_t)b * S * D + h * DEPTH;
    float* outp = g_attn + ((size_t)bh * S + j) * DEPTH;

    bool fast = false; int kwin = 0;
    if (cj > 0.f)      { fast = cj * (g_mx[bh] - g_mx2[bh]) > 90.f;  kwin = g_kmx[bh]; }
    else if (cj < 0.f) { fast = (-cj) * (g_mn2[bh] - g_mn[bh]) > 90.f; kwin = g_kmn[bh]; }

    if (fast) {
        float4 v = *(const float4*)(Vb + (size_t)kwin * D + lane * 4);
        *(float4*)(outp + lane * 4) = v;
    } else {
        // exact per-row softmax @ V  (rare / degenerate rows)
        float mj = (cj >= 0.f) ? cj * g_mx[bh] : cj * g_mn[bh];
        const float* A2 = g_A2 + bh * S;
        float den = 0.f;
        float4 acc = make_float4(0.f, 0.f, 0.f, 0.f);
        for (int k = 0; k < S; k++) {
            // clamp: true arg <= 0; FMA residual must not go positive -> inf
            float e = __expf(fminf(cj * A2[k] - mj, 0.f));
            den += e;
            float4 v = *(const float4*)(Vb + (size_t)k * D + lane * 4);
            acc.x = fmaf(e, v.x, acc.x);
            acc.y = fmaf(e, v.y, acc.y);
            acc.z = fmaf(e, v.z, acc.z);
            acc.w = fmaf(e, v.w, acc.w);
        }
        float inv = 1.f / den;
        acc.x *= inv; acc.y *= inv; acc.z *= inv; acc.w *= inv;
        *(float4*)(outp + lane * 4) = acc;
    }
}

// ------------------- LN(a + b) ----------------------------------------------
__global__ void k_ln(const float* __restrict__ xa, const float* __restrict__ xb,
                     const float* __restrict__ gam, const float* __restrict__ bet,
                     float* __restrict__ out) {
    int r = blockIdx.x, t = threadIdx.x;   // 256 threads, row of 1024
    const float* pa = xa + (size_t)r * D;
    const float* pb = xb + (size_t)r * D;
    float v[4];
    float s = 0.f;
#pragma unroll
    for (int i = 0; i < 4; i++) {
        int c = t + i * 256;
        v[i] = pa[c] + pb[c];
        s += v[i];
    }
    __shared__ float red[256];
    red[t] = s; __syncthreads();
    for (int o = 128; o > 0; o >>= 1) {
        if (t < o) red[t] += red[t + o];
        __syncthreads();
    }
    float mu = red[0] * (1.f / 1024.f);
    __syncthreads();
    float s2 = 0.f;
#pragma unroll
    for (int i = 0; i < 4; i++) { float d = v[i] - mu; s2 += d * d; }
    red[t] = s2; __syncthreads();
    for (int o = 128; o > 0; o >>= 1) {
        if (t < o) red[t] += red[t + o];
        __syncthreads();
    }
    float inv = rsqrtf(red[0] * (1.f / 1024.f) + EPSV);
    float* po = out + (size_t)r * D;
#pragma unroll
    for (int i = 0; i < 4; i++) {
        int c = t + i * 256;
        po[c] = (v[i] - mu) * inv * gam[c] + bet[c];
    }
}

// ------------------- launch --------------------------------------------------
extern "C" void kernel_launch(void* const* d_in, const int* in_sizes, int n_in,
                              void* d_out, int out_size) {
    const float* x    = (const float*)d_in[0];
    const float* wq   = (const float*)d_in[1];
    const float* wk   = (const float*)d_in[2];
    const float* wv   = (const float*)d_in[3];
    const float* rel  = (const float*)d_in[4];
    const float* w1   = (const float*)d_in[5];
    const float* b1   = (const float*)d_in[6];
    const float* w2   = (const float*)d_in[7];
    const float* b2   = (const float*)d_in[8];
    const float* ln1g = (const float*)d_in[9];
    const float* ln1b = (const float*)d_in[10];
    const float* ln2g = (const float*)d_in[11];
    const float* ln2b = (const float*)d_in[12];
    float* out = (float*)d_out;

    float *pYv, *pAttn, *pH1, *pMid, *pFfn;
    cudaGetSymbolAddress((void**)&pYv,   g_Yv);
    cudaGetSymbolAddress((void**)&pAttn, g_attn);
    cudaGetSymbolAddress((void**)&pH1,   g_h1);
    cudaGetSymbolAddress((void**)&pMid,  g_mid);
    cudaGetSymbolAddress((void**)&pFfn,  g_ffn);

    // qs / kts (reduced Q,K) and V GEMM
    k_wsum<<<(D * H + 255) / 256, 256>>>(wq, wk);
    k_qskts<<<R, 256>>>(x);
    k_sgemm<0><<<dim3(D / 128, R / 128), 256>>>(x, wv, nullptr, pYv, R, D, D);

    // rel_w reductions -> A2, SA1, extremes
    k_relw<<<dim3(S, BH), 256>>>(rel);
    k_finalize<<<BH, 256>>>();

    // softmax(c_j * A2) @ V  == one-hot gather (exact fallback inside)
    k_attn2<<<dim3(S / 16, BH), 256>>>();

    // LN1
    k_ln<<<R, 256>>>(x, pAttn, ln1g, ln1b, pH1);

    // FFN
    k_sgemm<1><<<dim3(DFF / 128, R / 128), 256>>>(pH1, w1, b1, pMid, R, DFF, D);
    k_sgemm<2><<<dim3(D / 128, R / 128), 256>>>(pMid, w2, b2, pFfn, R, D, DFF);

    // LN2 -> output
    k_ln<<<R, 256>>>(pH1, pFfn, ln2g, ln2b, out);
}

// round 5
// speedup vs baseline: 2.3882x; 2.3882x over previous
#include <cuda_runtime.h>
#include <cuda_bf16.h>
#include <math.h>
#include <float.h>
#include <stdint.h>

static constexpr int S = 1024;
static constexpr int Bd = 2;
static constexpr int D = 1024;
static constexpr int H = 16;
static constexpr int DEPTH = 64;
static constexpr int DFF = 4096;
static constexpr int R = S * Bd;      // 2048 token rows
static constexpr int BH = Bd * H;     // 32
static constexpr float SCALE = 0.125f;
static constexpr float NEGV = -1000000000.0f;
static constexpr float EPSV = 1e-5f;

// ------------------- scratch -------------------------------------------------
__device__ float g_Yv[R * D];
__device__ float g_attn[R * D];
__device__ float g_h1[R * D];
__device__ float g_ffn[R * D];
__device__ float g_wqsum[D * H];
__device__ float g_wksum[D * H];
__device__ float g_qsT[BH * S];
__device__ float g_ktsT[BH * S];
__device__ float g_A2[BH * S];
__device__ float g_P1[BH * S];
__device__ float g_SA1[BH];
__device__ float g_mx[BH];
__device__ float g_mn[BH];
__device__ float g_mx2[BH];
__device__ float g_mn2[BH];
__device__ int   g_kmx[BH];
__device__ int   g_kmn[BH];
// bf16 split operands
__device__ __nv_bfloat16 g_Xhi[R * D];
__device__ __nv_bfloat16 g_Xlo[R * D];
__device__ __nv_bfloat16 g_h1hi[R * D];
__device__ __nv_bfloat16 g_h1lo[R * D];
__device__ __nv_bfloat16 g_midhi[R * DFF];
__device__ __nv_bfloat16 g_midlo[R * DFF];
__device__ __nv_bfloat16 g_WvThi[D * D];
__device__ __nv_bfloat16 g_WvTlo[D * D];
__device__ __nv_bfloat16 g_W1Thi[DFF * D];
__device__ __nv_bfloat16 g_W1Tlo[DFF * D];
__device__ __nv_bfloat16 g_W2Thi[D * DFF];
__device__ __nv_bfloat16 g_W2Tlo[D * DFF];

// ------------------- PTX helpers (baseline sm_80+ features only) -------------
__device__ __forceinline__ uint32_t smem_to_u32(const void* p) {
    uint32_t a;
    asm("{ .reg .u64 t; cvta.to.shared.u64 t, %1; cvt.u32.u64 %0, t; }" : "=r"(a) : "l"(p));
    return a;
}
__device__ __forceinline__ void ldsm4(uint32_t* r, uint32_t addr) {
    asm volatile("ldmatrix.sync.aligned.m8n8.x4.shared.b16 {%0,%1,%2,%3}, [%4];"
        : "=r"(r[0]), "=r"(r[1]), "=r"(r[2]), "=r"(r[3]) : "r"(addr));
}
__device__ __forceinline__ void mma16816(float* d, const uint32_t* a, const uint32_t* b) {
    asm volatile(
        "mma.sync.aligned.m16n8k16.row.col.f32.bf16.bf16.f32 "
        "{%0,%1,%2,%3}, {%4,%5,%6,%7}, {%8,%9}, {%0,%1,%2,%3};"
        : "+f"(d[0]), "+f"(d[1]), "+f"(d[2]), "+f"(d[3])
        : "r"(a[0]), "r"(a[1]), "r"(a[2]), "r"(a[3]), "r"(b[0]), "r"(b[1]));
}
__device__ __forceinline__ void cpasync16(uint32_t saddr, const void* gaddr) {
    asm volatile("cp.async.cg.shared.global [%0], [%1], 16;" :: "r"(saddr), "l"(gaddr));
}
#define CP_COMMIT() asm volatile("cp.async.commit_group;" ::: "memory")
#define CP_WAIT1()  asm volatile("cp.async.wait_group 1;" ::: "memory")
#define CP_WAIT0()  asm volatile("cp.async.wait_group 0;" ::: "memory")

// ------------------- K0: column-group sums of Wq, Wk -----------------------
__global__ void k_wsum(const float* __restrict__ wq, const float* __restrict__ wk) {
    int idx = blockIdx.x * blockDim.x + threadIdx.x;
    if (idx >= D * H) return;
    int k = idx / H, h = idx % H;
    const float* p1 = wq + (size_t)k * D + h * DEPTH;
    const float* p2 = wk + (size_t)k * D + h * DEPTH;
    float s1 = 0.f, s2 = 0.f;
#pragma unroll 16
    for (int d = 0; d < DEPTH; d++) { s1 += p1[d]; s2 += p2[d]; }
    g_wqsum[k * H + h] = s1;
    g_wksum[k * H + h] = s2;
}

// ------------------- K1: qs / kts -------------------------------------------
__global__ void k_qskts(const float* __restrict__ x) {
    int r = blockIdx.x;
    int t = threadIdx.x;
    int h = t & 15, part = t >> 4;
    float a1 = 0.f, a2 = 0.f;
    const float* xr = x + (size_t)r * D;
    for (int k = part; k < D; k += 16) {
        float xv = xr[k];
        a1 += xv * g_wqsum[k * H + h];
        a2 += xv * g_wksum[k * H + h];
    }
    __shared__ float s1[16][16];
    __shared__ float s2[16][16];
    s1[part][h] = a1; s2[part][h] = a2;
    __syncthreads();
    if (t < H) {
        float q = 0.f, kk = 0.f;
#pragma unroll
        for (int p = 0; p < 16; p++) { q += s1[p][t]; kk += s2[p][t]; }
        int b = r >> 10, s = r & 1023;
        g_qsT[(b * H + t) * S + s]  = SCALE * q;
        g_ktsT[(b * H + t) * S + s] = kk;
    }
}

// ------------------- split X into bf16 hi/lo ---------------------------------
__global__ void k_split(const float* __restrict__ src, __nv_bfloat16* __restrict__ hi,
                        __nv_bfloat16* __restrict__ lo, int n4) {
    int i = blockIdx.x * blockDim.x + threadIdx.x;
    if (i >= n4) return;
    float4 v = ((const float4*)src)[i];
    __nv_bfloat162 h0 = __floats2bfloat162_rn(v.x, v.y);
    __nv_bfloat162 h1 = __floats2bfloat162_rn(v.z, v.w);
    __nv_bfloat162 l0 = __floats2bfloat162_rn(v.x - __bfloat162float(h0.x),
                                              v.y - __bfloat162float(h0.y));
    __nv_bfloat162 l1 = __floats2bfloat162_rn(v.z - __bfloat162float(h1.x),
                                              v.w - __bfloat162float(h1.y));
    ((__nv_bfloat162*)hi)[i * 2]     = h0;
    ((__nv_bfloat162*)hi)[i * 2 + 1] = h1;
    ((__nv_bfloat162*)lo)[i * 2]     = l0;
    ((__nv_bfloat162*)lo)[i * 2 + 1] = l1;
}

// ------------------- transpose + split: W[Kd][Nd] -> WT_hi/lo[Nd][Kd] --------
__global__ void k_trsp(const float* __restrict__ W, __nv_bfloat16* __restrict__ Thi,
                       __nv_bfloat16* __restrict__ Tlo, int Kd, int Nd) {
    __shared__ float tile[32][33];
    int n0 = blockIdx.x * 32, k0 = blockIdx.y * 32;
    int c = threadIdx.x & 31, rq = threadIdx.x >> 5;   // 256 threads
#pragma unroll
    for (int q = 0; q < 4; q++) {
        int kr = rq + q * 8;
        tile[kr][c] = W[(size_t)(k0 + kr) * Nd + n0 + c];
    }
    __syncthreads();
#pragma unroll
    for (int q = 0; q < 4; q++) {
        int nr = rq + q * 8;
        float v = tile[c][nr];
        __nv_bfloat16 h = __float2bfloat16_rn(v);
        __nv_bfloat16 l = __float2bfloat16_rn(v - __bfloat162float(h));
        Thi[(size_t)(n0 + nr) * Kd + k0 + c] = h;
        Tlo[(size_t)(n0 + nr) * Kd + k0 + c] = l;
    }
}

// ------------------- split-bf16 GEMM via mma.sync ----------------------------
// C(M,N) = A(M,K) @ B(N,K)^T, A/B given as bf16 hi/lo splits.
// EPI: 0 -> C fp32 ; 1 -> bias+relu -> Chi/Clo bf16 ; 2 -> bias -> C fp32
static constexpr int ROWB = 80;              // padded row bytes (32 bf16 + 8 pad)
static constexpr int TILEB = 128 * ROWB;     // 10240
static constexpr int BUFB = 4 * TILEB;       // 40960
static constexpr int GEMM_SMEM = 2 * BUFB;   // 81920

template <int EPI>
__global__ void __launch_bounds__(256)
mma_gemm(const __nv_bfloat16* __restrict__ Ahi, const __nv_bfloat16* __restrict__ Alo,
         const __nv_bfloat16* __restrict__ Bhi, const __nv_bfloat16* __restrict__ Blo,
         const float* __restrict__ bias, float* __restrict__ C,
         __nv_bfloat16* __restrict__ Chi, __nv_bfloat16* __restrict__ Clo,
         int M, int N, int K) {
    extern __shared__ char smem[];
    const uint32_t sbase = smem_to_u32(smem);
    int t = threadIdx.x;
    int lane = t & 31, wid = t >> 5;
    int wm = wid >> 2, wn = wid & 3;           // 2 x 4 warp grid
    int m0 = blockIdx.y * 128, n0 = blockIdx.x * 128;

    // global->smem mapping: thread t loads row lr, 32B half lh of each tile row
    int lr = t >> 1, lh = t & 1;
    const __nv_bfloat16* gsrc[4] = {
        Ahi + (size_t)(m0 + lr) * K + lh * 16,
        Alo + (size_t)(m0 + lr) * K + lh * 16,
        Bhi + (size_t)(n0 + lr) * K + lh * 16,
        Blo + (size_t)(n0 + lr) * K + lh * 16 };
    const uint32_t sdst = sbase + (uint32_t)(lr * ROWB + lh * 32);

    // ldmatrix lane address offsets
    uint32_t aoff = (uint32_t)((wm * 64 + ((lane >> 3) & 1) * 8 + (lane & 7)) * ROWB
                               + ((lane >> 4) & 1) * 16);
    uint32_t boff = (uint32_t)((wn * 32 + ((lane >> 4) & 1) * 8 + (lane & 7)) * ROWB
                               + ((lane >> 3) & 1) * 16);

    float acc[4][4][4];
#pragma unroll
    for (int i = 0; i < 4; i++)
#pragma unroll
        for (int j = 0; j < 4; j++)
#pragma unroll
            for (int e = 0; e < 4; e++) acc[i][j][e] = 0.f;

#define ISSUE(chunk, buf) do { \
    uint32_t _db = sdst + (uint32_t)(buf) * BUFB; \
    size_t _go = (size_t)(chunk) * 32; \
    _Pragma("unroll") \
    for (int _tl = 0; _tl < 4; _tl++) { \
        const __nv_bfloat16* _g = gsrc[_tl] + _go; \
        cpasync16(_db + _tl * TILEB,      _g); \
        cpasync16(_db + _tl * TILEB + 16, _g + 8); \
    } } while (0)

    const int NC = K >> 5;
    ISSUE(0, 0); CP_COMMIT();

    for (int c = 0; c < NC; c++) {
        int buf = c & 1;
        if (c + 1 < NC) { ISSUE(c + 1, buf ^ 1); CP_COMMIT(); CP_WAIT1(); }
        else            { CP_WAIT0(); }
        __syncthreads();
        uint32_t bb = sbase + (uint32_t)buf * BUFB;
#pragma unroll
        for (int s = 0; s < 2; s++) {
            uint32_t Ah[4][4], Al[4][4], Bh[2][4], Bl[2][4];
#pragma unroll
            for (int i = 0; i < 4; i++) {
                ldsm4(Ah[i], bb + aoff + i * 16 * ROWB + s * 32);
                ldsm4(Al[i], bb + TILEB + aoff + i * 16 * ROWB + s * 32);
            }
#pragma unroll
            for (int j2 = 0; j2 < 2; j2++) {
                ldsm4(Bh[j2], bb + 2 * TILEB + boff + j2 * 16 * ROWB + s * 32);
                ldsm4(Bl[j2], bb + 3 * TILEB + boff + j2 * 16 * ROWB + s * 32);
            }
#pragma unroll
            for (int i = 0; i < 4; i++)
#pragma unroll
                for (int j = 0; j < 4; j++) {
                    const uint32_t* bh = &Bh[j >> 1][(j & 1) * 2];
                    const uint32_t* bl = &Bl[j >> 1][(j & 1) * 2];
                    mma16816(acc[i][j], Ah[i], bh);
                    mma16816(acc[i][j], Ah[i], bl);
                    mma16816(acc[i][j], Al[i], bh);
                }
        }
        __syncthreads();
    }
#undef ISSUE

    // epilogue
    int r0 = lane >> 2, c2 = (lane & 3) * 2;
#pragma unroll
    for (int i = 0; i < 4; i++) {
#pragma unroll
        for (int j = 0; j < 4; j++) {
            int m = m0 + wm * 64 + i * 16 + r0;
            int n = n0 + wn * 32 + j * 8 + c2;
            float v0 = acc[i][j][0], v1 = acc[i][j][1];
            float v2 = acc[i][j][2], v3 = acc[i][j][3];
            if constexpr (EPI >= 1) {
                float b0 = bias[n], b1 = bias[n + 1];
                v0 += b0; v1 += b1; v2 += b0; v3 += b1;
            }
            if constexpr (EPI == 1) {
                v0 = fmaxf(v0, 0.f); v1 = fmaxf(v1, 0.f);
                v2 = fmaxf(v2, 0.f); v3 = fmaxf(v3, 0.f);
                __nv_bfloat162 h0 = __floats2bfloat162_rn(v0, v1);
                __nv_bfloat162 l0 = __floats2bfloat162_rn(v0 - __bfloat162float(h0.x),
                                                          v1 - __bfloat162float(h0.y));
                __nv_bfloat162 h1 = __floats2bfloat162_rn(v2, v3);
                __nv_bfloat162 l1 = __floats2bfloat162_rn(v2 - __bfloat162float(h1.x),
                                                          v3 - __bfloat162float(h1.y));
                *(__nv_bfloat162*)(Chi + (size_t)m * N + n)       = h0;
                *(__nv_bfloat162*)(Clo + (size_t)m * N + n)       = l0;
                *(__nv_bfloat162*)(Chi + (size_t)(m + 8) * N + n) = h1;
                *(__nv_bfloat162*)(Clo + (size_t)(m + 8) * N + n) = l1;
            } else {
                *(float2*)(C + (size_t)m * N + n)       = make_float2(v0, v1);
                *(float2*)(C + (size_t)(m + 8) * N + n) = make_float2(v2, v3);
            }
        }
    }
}

// ------------------- K3: rel_w weighted reductions ---------------------------
__global__ void k_relw(const float* __restrict__ rel) {
    int k = blockIdx.x;
    int bh = blockIdx.y;
    int t = threadIdx.x;
    const float* row = rel + ((size_t)bh * S + k) * S;
    const float* kts = g_ktsT + bh * S;
    float a1 = 0.f, a2 = 0.f;
    for (int m = t; m <= k; m += 256) {
        float rv  = row[1023 - k + m];
        float kv  = kts[m];
        float ktm = kv + NEGV * (float)min(m, 64);
        a1 += kv * rv;
        a2 += ktm * rv;
    }
    __shared__ float s1[256];
    __shared__ float s2[256];
    s1[t] = a1; s2[t] = a2;
    __syncthreads();
    for (int o = 128; o > 0; o >>= 1) {
        if (t < o) { s1[t] += s1[t + o]; s2[t] += s2[t + o]; }
        __syncthreads();
    }
    if (t == 0) {
        g_P1[bh * S + k] = s1[0];
        g_A2[bh * S + k] = s2[0];
    }
}

// ------------------- K4: SA1 + top-2 extremes per bh -------------------------
__global__ void k_finalize() {
    int bh = blockIdx.x, t = threadIdx.x;
    __shared__ float ss[256];
    __shared__ float sv[256];
    __shared__ int   si[256];
    __shared__ float sw_[256];
    __shared__ int   sj[256];
    const float* A2 = g_A2 + bh * S;
    float sa = 0.f, mx = -FLT_MAX, mn = FLT_MAX;
    int im = 0, imn = 0;
    for (int k = t; k < S; k += 256) {
        sa += g_P1[bh * S + k];
        float a = A2[k];
        if (a > mx) { mx = a; im = k; }
        if (a < mn) { mn = a; imn = k; }
    }
    ss[t] = sa; sv[t] = mx; si[t] = im; sw_[t] = mn; sj[t] = imn;
    __syncthreads();
    for (int o = 128; o > 0; o >>= 1) {
        if (t < o) {
            ss[t] += ss[t + o];
            if (sv[t + o] > sv[t]) { sv[t] = sv[t + o]; si[t] = si[t + o]; }
            if (sw_[t + o] < sw_[t]) { sw_[t] = sw_[t + o]; sj[t] = sj[t + o]; }
        }
        __syncthreads();
    }
    int kmx = si[0], kmn = sj[0];
    float vmx = sv[0], vmn = sw_[0], vsa = ss[0];
    __syncthreads();
    float mx2 = -FLT_MAX, mn2 = FLT_MAX;
    for (int k = t; k < S; k += 256) {
        float a = A2[k];
        if (k != kmx && a > mx2) mx2 = a;
        if (k != kmn && a < mn2) mn2 = a;
    }
    sv[t] = mx2; sw_[t] = mn2;
    __syncthreads();
    for (int o = 128; o > 0; o >>= 1) {
        if (t < o) { sv[t] = fmaxf(sv[t], sv[t + o]); sw_[t] = fminf(sw_[t], sw_[t + o]); }
        __syncthreads();
    }
    if (t == 0) {
        g_SA1[bh] = vsa;
        g_mx[bh] = vmx; g_mn[bh] = vmn;
        g_mx2[bh] = sv[0]; g_mn2[bh] = sw_[0];
        g_kmx[bh] = kmx; g_kmn[bh] = kmn;
    }
}

// ------------------- K5: one-hot gather + exact fallback ---------------------
__global__ void __launch_bounds__(256) k_attn2() {
    int bh = blockIdx.y;
    int b = bh >> 4, h = bh & 15;
    int t = threadIdx.x;
    int rg = t >> 4;
    int lane = t & 15;
    int j = blockIdx.x * 16 + rg;

    float cj = SCALE * g_qsT[bh * S + j] * g_SA1[bh];
    const float* Vb = g_Yv + (size_t)b * S * D + h * DEPTH;
    float* outp = g_attn + ((size_t)bh * S + j) * DEPTH;

    bool fast = false; int kwin = 0;
    if (cj > 0.f)      { fast = cj * (g_mx[bh] - g_mx2[bh]) > 90.f;  kwin = g_kmx[bh]; }
    else if (cj < 0.f) { fast = (-cj) * (g_mn2[bh] - g_mn[bh]) > 90.f; kwin = g_kmn[bh]; }

    if (fast) {
        float4 v = *(const float4*)(Vb + (size_t)kwin * D + lane * 4);
        *(float4*)(outp + lane * 4) = v;
    } else {
        float mj = (cj >= 0.f) ? cj * g_mx[bh] : cj * g_mn[bh];
        const float* A2 = g_A2 + bh * S;
        float den = 0.f;
        float4 acc = make_float4(0.f, 0.f, 0.f, 0.f);
        for (int k = 0; k < S; k++) {
            float e = __expf(fminf(cj * A2[k] - mj, 0.f));
            den += e;
            float4 v = *(const float4*)(Vb + (size_t)k * D + lane * 4);
            acc.x = fmaf(e, v.x, acc.x);
            acc.y = fmaf(e, v.y, acc.y);
            acc.z = fmaf(e, v.z, acc.z);
            acc.w = fmaf(e, v.w, acc.w);
        }
        float inv = 1.f / den;
        acc.x *= inv; acc.y *= inv; acc.z *= inv; acc.w *= inv;
        *(float4*)(outp + lane * 4) = acc;
    }
}

// ------------------- LN(a + b) [optionally emit bf16 hi/lo split] ------------
template <int SPLIT>
__global__ void k_ln(const float* __restrict__ xa, const float* __restrict__ xb,
                     const float* __restrict__ gam, const float* __restrict__ bet,
                     float* __restrict__ out,
                     __nv_bfloat16* __restrict__ ohi, __nv_bfloat16* __restrict__ olo) {
    int r = blockIdx.x, t = threadIdx.x;
    const float* pa = xa + (size_t)r * D;
    const float* pb = xb + (size_t)r * D;
    float v[4];
    float s = 0.f;
#pragma unroll
    for (int i = 0; i < 4; i++) {
        int c = t + i * 256;
        v[i] = pa[c] + pb[c];
        s += v[i];
    }
    __shared__ float red[256];
    red[t] = s; __syncthreads();
    for (int o = 128; o > 0; o >>= 1) {
        if (t < o) red[t] += red[t + o];
        __syncthreads();
    }
    float mu = red[0] * (1.f / 1024.f);
    __syncthreads();
    float s2 = 0.f;
#pragma unroll
    for (int i = 0; i < 4; i++) { float dd = v[i] - mu; s2 += dd * dd; }
    red[t] = s2; __syncthreads();
    for (int o = 128; o > 0; o >>= 1) {
        if (t < o) red[t] += red[t + o];
        __syncthreads();
    }
    float inv = rsqrtf(red[0] * (1.f / 1024.f) + EPSV);
    float* po = out + (size_t)r * D;
#pragma unroll
    for (int i = 0; i < 4; i++) {
        int c = t + i * 256;
        float y = (v[i] - mu) * inv * gam[c] + bet[c];
        po[c] = y;
        if constexpr (SPLIT) {
            __nv_bfloat16 hh = __float2bfloat16_rn(y);
            ohi[(size_t)r * D + c] = hh;
            olo[(size_t)r * D + c] = __float2bfloat16_rn(y - __bfloat162float(hh));
        }
    }
}

// ------------------- launch ---------------------------------------------------
extern "C" void kernel_launch(void* const* d_in, const int* in_sizes, int n_in,
                              void* d_out, int out_size) {
    const float* x    = (const float*)d_in[0];
    const float* wq   = (const float*)d_in[1];
    const float* wk   = (const float*)d_in[2];
    const float* wv   = (const float*)d_in[3];
    const float* rel  = (const float*)d_in[4];
    const float* w1   = (const float*)d_in[5];
    const float* b1   = (const float*)d_in[6];
    const float* w2   = (const float*)d_in[7];
    const float* b2   = (const float*)d_in[8];
    const float* ln1g = (const float*)d_in[9];
    const float* ln1b = (const float*)d_in[10];
    const float* ln2g = (const float*)d_in[11];
    const float* ln2b = (const float*)d_in[12];
    float* out = (float*)d_out;

    cudaFuncSetAttribute(mma_gemm<0>, cudaFuncAttributeMaxDynamicSharedMemorySize, GEMM_SMEM);
    cudaFuncSetAttribute(mma_gemm<1>, cudaFuncAttributeMaxDynamicSharedMemorySize, GEMM_SMEM);
    cudaFuncSetAttribute(mma_gemm<2>, cudaFuncAttributeMaxDynamicSharedMemorySize, GEMM_SMEM);

    float *pYv, *pAttn, *pH1, *pFfn;
    __nv_bfloat16 *pXhi, *pXlo, *pH1hi, *pH1lo, *pMhi, *pMlo;
    __nv_bfloat16 *pWvh, *pWvl, *pW1h, *pW1l, *pW2h, *pW2l;
    cudaGetSymbolAddress((void**)&pYv,   g_Yv);
    cudaGetSymbolAddress((void**)&pAttn, g_attn);
    cudaGetSymbolAddress((void**)&pH1,   g_h1);
    cudaGetSymbolAddress((void**)&pFfn,  g_ffn);
    cudaGetSymbolAddress((void**)&pXhi,  g_Xhi);
    cudaGetSymbolAddress((void**)&pXlo,  g_Xlo);
    cudaGetSymbolAddress((void**)&pH1hi, g_h1hi);
    cudaGetSymbolAddress((void**)&pH1lo, g_h1lo);
    cudaGetSymbolAddress((void**)&pMhi,  g_midhi);
    cudaGetSymbolAddress((void**)&pMlo,  g_midlo);
    cudaGetSymbolAddress((void**)&pWvh,  g_WvThi);
    cudaGetSymbolAddress((void**)&pWvl,  g_WvTlo);
    cudaGetSymbolAddress((void**)&pW1h,  g_W1Thi);
    cudaGetSymbolAddress((void**)&pW1l,  g_W1Tlo);
    cudaGetSymbolAddress((void**)&pW2h,  g_W2Thi);
    cudaGetSymbolAddress((void**)&pW2l,  g_W2Tlo);

    // prep: splits + weight transposes
    k_split<<<(R * D / 4 + 255) / 256, 256>>>(x, pXhi, pXlo, R * D / 4);
    k_trsp<<<dim3(D / 32, D / 32), 256>>>(wv, pWvh, pWvl, D, D);
    k_trsp<<<dim3(DFF / 32, D / 32), 256>>>(w1, pW1h, pW1l, D, DFF);
    k_trsp<<<dim3(D / 32, DFF / 32), 256>>>(w2, pW2h, pW2l, DFF, D);

    // reduced Q,K path
    k_wsum<<<(D * H + 255) / 256, 256>>>(wq, wk);
    k_qskts<<<R, 256>>>(x);

    // V = X @ Wv  (tensor cores, split bf16)
    mma_gemm<0><<<dim3(D / 128, R / 128), 256, GEMM_SMEM>>>(
        pXhi, pXlo, pWvh, pWvl, nullptr, pYv, nullptr, nullptr, R, D, D);

    // rel_w reductions -> A2, SA1, extremes
    k_relw<<<dim3(S, BH), 256>>>(rel);
    k_finalize<<<BH, 256>>>();

    // one-hot softmax @ V
    k_attn2<<<dim3(S / 16, BH), 256>>>();

    // LN1 (+ bf16 split of h1)
    k_ln<1><<<R, 256>>>(x, pAttn, ln1g, ln1b, pH1, pH1hi, pH1lo);

    // FFN GEMM1: mid = relu(h1 @ w1 + b1) -> bf16 hi/lo
    mma_gemm<1><<<dim3(DFF / 128, R / 128), 256, GEMM_SMEM>>>(
        pH1hi, pH1lo, pW1h, pW1l, b1, nullptr, pMhi, pMlo, R, DFF, D);

    // FFN GEMM2: ffn = mid @ w2 + b2
    mma_gemm<2><<<dim3(D / 128, R / 128), 256, GEMM_SMEM>>>(
        pMhi, pMlo, pW2h, pW2l, b2, pFfn, nullptr, nullptr, R, D, DFF);

    // LN2 -> output
    k_ln<0><<<R, 256>>>(pH1, pFfn, ln2g, ln2b, out, nullptr, nullptr);
}

// round 6
// speedup vs baseline: 3.2118x; 1.3449x over previous
#include <cuda_runtime.h>
#include <cuda_fp16.h>
#include <math.h>
#include <float.h>
#include <stdint.h>

static constexpr int S = 1024;
static constexpr int Bd = 2;
static constexpr int D = 1024;
static constexpr int H = 16;
static constexpr int DEPTH = 64;
static constexpr int DFF = 4096;
static constexpr int R = S * Bd;      // 2048 token rows
static constexpr int BH = Bd * H;     // 32
static constexpr float SCALE = 0.125f;
static constexpr float NEGV = -1000000000.0f;
static constexpr float EPSV = 1e-5f;

// ------------------- scratch -------------------------------------------------
__device__ float g_Yv[R * D];
__device__ float g_attn[R * D];
__device__ float g_h1[R * D];
__device__ float g_ffn[R * D];
__device__ float g_wqsum[D * H];
__device__ float g_wksum[D * H];
__device__ float g_qsT[BH * S];
__device__ float g_ktsT[BH * S];
__device__ float g_A2[BH * S];
__device__ float g_P1[BH * S];
__device__ float g_SA1[BH];
__device__ float g_mx[BH];
__device__ float g_mn[BH];
__device__ float g_mx2[BH];
__device__ float g_mn2[BH];
__device__ int   g_kmx[BH];
__device__ int   g_kmn[BH];
// fp16 operands: A-side single, B-side hi/lo split
__device__ __half g_Xh[R * D];
__device__ __half g_h1h[R * D];
__device__ __half g_midh[R * DFF];
__device__ __half g_WvThi[D * D];
__device__ __half g_WvTlo[D * D];
__device__ __half g_W1Thi[DFF * D];
__device__ __half g_W1Tlo[DFF * D];
__device__ __half g_W2Thi[D * DFF];
__device__ __half g_W2Tlo[D * DFF];

// ------------------- PTX helpers (baseline sm_80+ features only) -------------
__device__ __forceinline__ uint32_t smem_to_u32(const void* p) {
    uint32_t a;
    asm("{ .reg .u64 t; cvta.to.shared.u64 t, %1; cvt.u32.u64 %0, t; }" : "=r"(a) : "l"(p));
    return a;
}
__device__ __forceinline__ void ldsm4(uint32_t* r, uint32_t addr) {
    asm volatile("ldmatrix.sync.aligned.m8n8.x4.shared.b16 {%0,%1,%2,%3}, [%4];"
        : "=r"(r[0]), "=r"(r[1]), "=r"(r[2]), "=r"(r[3]) : "r"(addr));
}
__device__ __forceinline__ void mma16816(float* d, const uint32_t* a, const uint32_t* b) {
    asm volatile(
        "mma.sync.aligned.m16n8k16.row.col.f32.f16.f16.f32 "
        "{%0,%1,%2,%3}, {%4,%5,%6,%7}, {%8,%9}, {%0,%1,%2,%3};"
        : "+f"(d[0]), "+f"(d[1]), "+f"(d[2]), "+f"(d[3])
        : "r"(a[0]), "r"(a[1]), "r"(a[2]), "r"(a[3]), "r"(b[0]), "r"(b[1]));
}
__device__ __forceinline__ void cpasync16(uint32_t saddr, const void* gaddr) {
    asm volatile("cp.async.cg.shared.global [%0], [%1], 16;" :: "r"(saddr), "l"(gaddr));
}
#define CP_COMMIT() asm volatile("cp.async.commit_group;" ::: "memory")
#define CP_WAIT2()  asm volatile("cp.async.wait_group 2;" ::: "memory")
#define CP_WAIT1()  asm volatile("cp.async.wait_group 1;" ::: "memory")
#define CP_WAIT0()  asm volatile("cp.async.wait_group 0;" ::: "memory")

// ------------------- K0: column-group sums of Wq, Wk -----------------------
__global__ void k_wsum(const float* __restrict__ wq, const float* __restrict__ wk) {
    int idx = blockIdx.x * blockDim.x + threadIdx.x;
    if (idx >= D * H) return;
    int k = idx / H, h = idx % H;
    const float* p1 = wq + (size_t)k * D + h * DEPTH;
    const float* p2 = wk + (size_t)k * D + h * DEPTH;
    float s1 = 0.f, s2 = 0.f;
#pragma unroll 16
    for (int d = 0; d < DEPTH; d++) { s1 += p1[d]; s2 += p2[d]; }
    g_wqsum[k * H + h] = s1;
    g_wksum[k * H + h] = s2;
}

// ------------------- K1: qs / kts -------------------------------------------
__global__ void k_qskts(const float* __restrict__ x) {
    int r = blockIdx.x;
    int t = threadIdx.x;
    int h = t & 15, part = t >> 4;
    float a1 = 0.f, a2 = 0.f;
    const float* xr = x + (size_t)r * D;
    for (int k = part; k < D; k += 16) {
        float xv = xr[k];
        a1 += xv * g_wqsum[k * H + h];
        a2 += xv * g_wksum[k * H + h];
    }
    __shared__ float s1[16][16];
    __shared__ float s2[16][16];
    s1[part][h] = a1; s2[part][h] = a2;
    __syncthreads();
    if (t < H) {
        float q = 0.f, kk = 0.f;
#pragma unroll
        for (int p = 0; p < 16; p++) { q += s1[p][t]; kk += s2[p][t]; }
        int b = r >> 10, s = r & 1023;
        g_qsT[(b * H + t) * S + s]  = SCALE * q;
        g_ktsT[(b * H + t) * S + s] = kk;
    }
}

// ------------------- split X into single fp16 ---------------------------------
__global__ void k_split(const float* __restrict__ src, __half* __restrict__ dst, int n4) {
    int i = blockIdx.x * blockDim.x + threadIdx.x;
    if (i >= n4) return;
    float4 v = ((const float4*)src)[i];
    ((__half2*)dst)[i * 2]     = __floats2half2_rn(v.x, v.y);
    ((__half2*)dst)[i * 2 + 1] = __floats2half2_rn(v.z, v.w);
}

// ------------------- transpose + split: W[Kd][Nd] -> WT_hi/lo[Nd][Kd] --------
__global__ void k_trsp(const float* __restrict__ W, __half* __restrict__ Thi,
                       __half* __restrict__ Tlo, int Kd, int Nd) {
    __shared__ float tile[32][33];
    int n0 = blockIdx.x * 32, k0 = blockIdx.y * 32;
    int c = threadIdx.x & 31, rq = threadIdx.x >> 5;   // 256 threads
#pragma unroll
    for (int q = 0; q < 4; q++) {
        int kr = rq + q * 8;
        tile[kr][c] = W[(size_t)(k0 + kr) * Nd + n0 + c];
    }
    __syncthreads();
#pragma unroll
    for (int q = 0; q < 4; q++) {
        int nr = rq + q * 8;
        float v = tile[c][nr];
        __half h = __float2half_rn(v);
        __half l = __float2half_rn(v - __half2float(h));
        Thi[(size_t)(n0 + nr) * Kd + k0 + c] = h;
        Tlo[(size_t)(n0 + nr) * Kd + k0 + c] = l;
    }
}

// ------------------- 2-pass fp16 GEMM via mma.sync ----------------------------
// C(M,N) = A(M,K) @ B(N,K)^T, A single fp16, B split hi/lo fp16.
// EPI: 0 -> C fp32 ; 1 -> bias+relu -> Ch fp16 ; 2 -> bias -> C fp32
static constexpr int ROWB = 80;              // 32 fp16 (64B) + 16B pad
static constexpr int TILEB = 128 * ROWB;     // 10240
static constexpr int BUFB = 3 * TILEB;       // 30720 (A, Bhi, Blo)
static constexpr int NSTAGE = 3;
static constexpr int GEMM_SMEM = NSTAGE * BUFB;   // 92160

template <int EPI>
__global__ void __launch_bounds__(256, 2)
mma_gemm(const __half* __restrict__ A,
         const __half* __restrict__ Bhi, const __half* __restrict__ Blo,
         const float* __restrict__ bias, float* __restrict__ C,
         __half* __restrict__ Ch,
         int M, int N, int K) {
    extern __shared__ char smem[];
    const uint32_t sbase = smem_to_u32(smem);
    int t = threadIdx.x;
    int lane = t & 31, wid = t >> 5;
    int wm = wid >> 2, wn = wid & 3;           // 2 x 4 warp grid
    int m0 = blockIdx.y * 128, n0 = blockIdx.x * 128;

    // global->smem: thread t loads row lr, 32B half lh of each 64B tile row
    int lr = t >> 1, lh = t & 1;
    const __half* gsrc[3] = {
        A   + (size_t)(m0 + lr) * K + lh * 16,
        Bhi + (size_t)(n0 + lr) * K + lh * 16,
        Blo + (size_t)(n0 + lr) * K + lh * 16 };
    const uint32_t sdst = sbase + (uint32_t)(lr * ROWB + lh * 32);

    // ldmatrix lane address offsets
    uint32_t aoff = (uint32_t)((wm * 64 + ((lane >> 3) & 1) * 8 + (lane & 7)) * ROWB
                               + ((lane >> 4) & 1) * 16);
    uint32_t boff = (uint32_t)((wn * 32 + ((lane >> 4) & 1) * 8 + (lane & 7)) * ROWB
                               + ((lane >> 3) & 1) * 16);

    float acc[4][4][4];
#pragma unroll
    for (int i = 0; i < 4; i++)
#pragma unroll
        for (int j = 0; j < 4; j++)
#pragma unroll
            for (int e = 0; e < 4; e++) acc[i][j][e] = 0.f;

#define ISSUE(chunk, buf) do { \
    uint32_t _db = sdst + (uint32_t)(buf) * BUFB; \
    size_t _go = (size_t)(chunk) * 32; \
    _Pragma("unroll") \
    for (int _tl = 0; _tl < 3; _tl++) { \
        const __half* _g = gsrc[_tl] + _go; \
        cpasync16(_db + _tl * TILEB,      _g); \
        cpasync16(_db + _tl * TILEB + 16, _g + 8); \
    } } while (0)

    const int NC = K >> 5;
    ISSUE(0, 0); CP_COMMIT();
    ISSUE(1, 1); CP_COMMIT();

    int buf = 0;
    for (int c = 0; c < NC; c++) {
        if (c + 2 < NC) {
            int nb = buf + 2; if (nb >= NSTAGE) nb -= NSTAGE;
            ISSUE(c + 2, nb); CP_COMMIT(); CP_WAIT2();
        } else if (c + 1 < NC) {
            CP_WAIT1();
        } else {
            CP_WAIT0();
        }
        __syncthreads();
        uint32_t bb = sbase + (uint32_t)buf * BUFB;
#pragma unroll
        for (int s = 0; s < 2; s++) {
            uint32_t Ah[4][4], Bh[2][4], Bl[2][4];
#pragma unroll
            for (int i = 0; i < 4; i++)
                ldsm4(Ah[i], bb + aoff + i * 16 * ROWB + s * 32);
#pragma unroll
            for (int j2 = 0; j2 < 2; j2++) {
                ldsm4(Bh[j2], bb + TILEB + boff + j2 * 16 * ROWB + s * 32);
                ldsm4(Bl[j2], bb + 2 * TILEB + boff + j2 * 16 * ROWB + s * 32);
            }
#pragma unroll
            for (int i = 0; i < 4; i++)
#pragma unroll
                for (int j = 0; j < 4; j++) {
                    const uint32_t* bh = &Bh[j >> 1][(j & 1) * 2];
                    const uint32_t* bl = &Bl[j >> 1][(j & 1) * 2];
                    mma16816(acc[i][j], Ah[i], bh);
                    mma16816(acc[i][j], Ah[i], bl);
                }
        }
        __syncthreads();
        if (++buf == NSTAGE) buf = 0;
    }
#undef ISSUE

    // epilogue
    int r0 = lane >> 2, c2 = (lane & 3) * 2;
#pragma unroll
    for (int i = 0; i < 4; i++) {
#pragma unroll
        for (int j = 0; j < 4; j++) {
            int m = m0 + wm * 64 + i * 16 + r0;
            int n = n0 + wn * 32 + j * 8 + c2;
            float v0 = acc[i][j][0], v1 = acc[i][j][1];
            float v2 = acc[i][j][2], v3 = acc[i][j][3];
            if constexpr (EPI >= 1) {
                float b0 = bias[n], b1 = bias[n + 1];
                v0 += b0; v1 += b1; v2 += b0; v3 += b1;
            }
            if constexpr (EPI == 1) {
                v0 = fmaxf(v0, 0.f); v1 = fmaxf(v1, 0.f);
                v2 = fmaxf(v2, 0.f); v3 = fmaxf(v3, 0.f);
                *(__half2*)(Ch + (size_t)m * N + n)       = __floats2half2_rn(v0, v1);
                *(__half2*)(Ch + (size_t)(m + 8) * N + n) = __floats2half2_rn(v2, v3);
            } else {
                *(float2*)(C + (size_t)m * N + n)       = make_float2(v0, v1);
                *(float2*)(C + (size_t)(m + 8) * N + n) = make_float2(v2, v3);
            }
        }
    }
}

// ------------------- K3: rel_w weighted reductions (balanced pairs) ----------
// Block handles k1 = p and k2 = 1023-p: total work 1025 elements, constant.
__global__ void k_relw(const float* __restrict__ rel) {
    int p = blockIdx.x;       // 0..511
    int bh = blockIdx.y;      // 0..31
    int t = threadIdx.x;      // 256
    int k1 = p, k2 = 1023 - p;
    const float* kts = g_ktsT + bh * S;
    const float* r1 = rel + ((size_t)bh * S + k1) * S + (1023 - k1);
    const float* r2 = rel + ((size_t)bh * S + k2) * S + (1023 - k2);
    float s11 = 0.f, s12 = 0.f, s21 = 0.f, s22 = 0.f;
    for (int m = t; m <= k1; m += 256) {
        float rv = r1[m], kv = kts[m];
        s11 += kv * rv;
        s12 += (kv + NEGV * (float)min(m, 64)) * rv;
    }
    for (int m = t; m <= k2; m += 256) {
        float rv = r2[m], kv = kts[m];
        s21 += kv * rv;
        s22 += (kv + NEGV * (float)min(m, 64)) * rv;
    }
    __shared__ float4 red[256];
    red[t] = make_float4(s11, s12, s21, s22);
    __syncthreads();
    for (int o = 128; o > 0; o >>= 1) {
        if (t < o) {
            float4 a = red[t], b = red[t + o];
            red[t] = make_float4(a.x + b.x, a.y + b.y, a.z + b.z, a.w + b.w);
        }
        __syncthreads();
    }
    if (t == 0) {
        float4 v = red[0];
        g_P1[bh * S + k1] = v.x;
        g_A2[bh * S + k1] = v.y;
        g_P1[bh * S + k2] = v.z;
        g_A2[bh * S + k2] = v.w;
    }
}

// ------------------- K4: SA1 + top-2 extremes per bh -------------------------
__global__ void k_finalize() {
    int bh = blockIdx.x, t = threadIdx.x;
    __shared__ float ss[256];
    __shared__ float sv[256];
    __shared__ int   si[256];
    __shared__ float sw_[256];
    __shared__ int   sj[256];
    const float* A2 = g_A2 + bh * S;
    float sa = 0.f, mx = -FLT_MAX, mn = FLT_MAX;
    int im = 0, imn = 0;
    for (int k = t; k < S; k += 256) {
        sa += g_P1[bh * S + k];
        float a = A2[k];
        if (a > mx) { mx = a; im = k; }
        if (a < mn) { mn = a; imn = k; }
    }
    ss[t] = sa; sv[t] = mx; si[t] = im; sw_[t] = mn; sj[t] = imn;
    __syncthreads();
    for (int o = 128; o > 0; o >>= 1) {
        if (t < o) {
            ss[t] += ss[t + o];
            if (sv[t + o] > sv[t]) { sv[t] = sv[t + o]; si[t] = si[t + o]; }
            if (sw_[t + o] < sw_[t]) { sw_[t] = sw_[t + o]; sj[t] = sj[t + o]; }
        }
        __syncthreads();
    }
    int kmx = si[0], kmn = sj[0];
    float vmx = sv[0], vmn = sw_[0], vsa = ss[0];
    __syncthreads();
    float mx2 = -FLT_MAX, mn2 = FLT_MAX;
    for (int k = t; k < S; k += 256) {
        float a = A2[k];
        if (k != kmx && a > mx2) mx2 = a;
        if (k != kmn && a < mn2) mn2 = a;
    }
    sv[t] = mx2; sw_[t] = mn2;
    __syncthreads();
    for (int o = 128; o > 0; o >>= 1) {
        if (t < o) { sv[t] = fmaxf(sv[t], sv[t + o]); sw_[t] = fminf(sw_[t], sw_[t + o]); }
        __syncthreads();
    }
    if (t == 0) {
        g_SA1[bh] = vsa;
        g_mx[bh] = vmx; g_mn[bh] = vmn;
        g_mx2[bh] = sv[0]; g_mn2[bh] = sw_[0];
        g_kmx[bh] = kmx; g_kmn[bh] = kmn;
    }
}

// ------------------- K5: one-hot gather + exact fallback ---------------------
__global__ void __launch_bounds__(256) k_attn2() {
    int bh = blockIdx.y;
    int b = bh >> 4, h = bh & 15;
    int t = threadIdx.x;
    int rg = t >> 4;
    int lane = t & 15;
    int j = blockIdx.x * 16 + rg;

    float cj = SCALE * g_qsT[bh * S + j] * g_SA1[bh];
    const float* Vb = g_Yv + (size_t)b * S * D + h * DEPTH;
    float* outp = g_attn + ((size_t)bh * S + j) * DEPTH;

    bool fast = false; int kwin = 0;
    if (cj > 0.f)      { fast = cj * (g_mx[bh] - g_mx2[bh]) > 90.f;  kwin = g_kmx[bh]; }
    else if (cj < 0.f) { fast = (-cj) * (g_mn2[bh] - g_mn[bh]) > 90.f; kwin = g_kmn[bh]; }

    if (fast) {
        float4 v = *(const float4*)(Vb + (size_t)kwin * D + lane * 4);
        *(float4*)(outp + lane * 4) = v;
    } else {
        float mj = (cj >= 0.f) ? cj * g_mx[bh] : cj * g_mn[bh];
        const float* A2 = g_A2 + bh * S;
        float den = 0.f;
        float4 acc = make_float4(0.f, 0.f, 0.f, 0.f);
        for (int k = 0; k < S; k++) {
            float e = __expf(fminf(cj * A2[k] - mj, 0.f));
            den += e;
            float4 v = *(const float4*)(Vb + (size_t)k * D + lane * 4);
            acc.x = fmaf(e, v.x, acc.x);
            acc.y = fmaf(e, v.y, acc.y);
            acc.z = fmaf(e, v.z, acc.z);
            acc.w = fmaf(e, v.w, acc.w);
        }
        float inv = 1.f / den;
        acc.x *= inv; acc.y *= inv; acc.z *= inv; acc.w *= inv;
        *(float4*)(outp + lane * 4) = acc;
    }
}

// ------------------- LN(a + b) [optionally emit fp16] ------------------------
template <int SPLIT>
__global__ void k_ln(const float* __restrict__ xa, const float* __restrict__ xb,
                     const float* __restrict__ gam, const float* __restrict__ bet,
                     float* __restrict__ out, __half* __restrict__ oh) {
    int r = blockIdx.x, t = threadIdx.x;
    const float* pa = xa + (size_t)r * D;
    const float* pb = xb + (size_t)r * D;
    float v[4];
    float s = 0.f;
#pragma unroll
    for (int i = 0; i < 4; i++) {
        int c = t + i * 256;
        v[i] = pa[c] + pb[c];
        s += v[i];
    }
    __shared__ float red[256];
    red[t] = s; __syncthreads();
    for (int o = 128; o > 0; o >>= 1) {
        if (t < o) red[t] += red[t + o];
        __syncthreads();
    }
    float mu = red[0] * (1.f / 1024.f);
    __syncthreads();
    float s2 = 0.f;
#pragma unroll
    for (int i = 0; i < 4; i++) { float dd = v[i] - mu; s2 += dd * dd; }
    red[t] = s2; __syncthreads();
    for (int o = 128; o > 0; o >>= 1) {
        if (t < o) red[t] += red[t + o];
        __syncthreads();
    }
    float inv = rsqrtf(red[0] * (1.f / 1024.f) + EPSV);
    float* po = out + (size_t)r * D;
#pragma unroll
    for (int i = 0; i < 4; i++) {
        int c = t + i * 256;
        float y = (v[i] - mu) * inv * gam[c] + bet[c];
        po[c] = y;
        if constexpr (SPLIT) oh[(size_t)r * D + c] = __float2half_rn(y);
    }
}

// ------------------- launch ---------------------------------------------------
extern "C" void kernel_launch(void* const* d_in, const int* in_sizes, int n_in,
                              void* d_out, int out_size) {
    const float* x    = (const float*)d_in[0];
    const float* wq   = (const float*)d_in[1];
    const float* wk   = (const float*)d_in[2];
    const float* wv   = (const float*)d_in[3];
    const float* rel  = (const float*)d_in[4];
    const float* w1   = (const float*)d_in[5];
    const float* b1   = (const float*)d_in[6];
    const float* w2   = (const float*)d_in[7];
    const float* b2   = (const float*)d_in[8];
    const float* ln1g = (const float*)d_in[9];
    const float* ln1b = (const float*)d_in[10];
    const float* ln2g = (const float*)d_in[11];
    const float* ln2b = (const float*)d_in[12];
    float* out = (float*)d_out;

    cudaFuncSetAttribute(mma_gemm<0>, cudaFuncAttributeMaxDynamicSharedMemorySize, GEMM_SMEM);
    cudaFuncSetAttribute(mma_gemm<1>, cudaFuncAttributeMaxDynamicSharedMemorySize, GEMM_SMEM);
    cudaFuncSetAttribute(mma_gemm<2>, cudaFuncAttributeMaxDynamicSharedMemorySize, GEMM_SMEM);

    float *pYv, *pAttn, *pH1, *pFfn;
    __half *pXh, *pH1h, *pMh;
    __half *pWvh, *pWvl, *pW1h, *pW1l, *pW2h, *pW2l;
    cudaGetSymbolAddress((void**)&pYv,   g_Yv);
    cudaGetSymbolAddress((void**)&pAttn, g_attn);
    cudaGetSymbolAddress((void**)&pH1,   g_h1);
    cudaGetSymbolAddress((void**)&pFfn,  g_ffn);
    cudaGetSymbolAddress((void**)&pXh,   g_Xh);
    cudaGetSymbolAddress((void**)&pH1h,  g_h1h);
    cudaGetSymbolAddress((void**)&pMh,   g_midh);
    cudaGetSymbolAddress((void**)&pWvh,  g_WvThi);
    cudaGetSymbolAddress((void**)&pWvl,  g_WvTlo);
    cudaGetSymbolAddress((void**)&pW1h,  g_W1Thi);
    cudaGetSymbolAddress((void**)&pW1l,  g_W1Tlo);
    cudaGetSymbolAddress((void**)&pW2h,  g_W2Thi);
    cudaGetSymbolAddress((void**)&pW2l,  g_W2Tlo);

    // prep: split + weight transposes
    k_split<<<(R * D / 4 + 255) / 256, 256>>>(x, pXh, R * D / 4);
    k_trsp<<<dim3(D / 32, D / 32), 256>>>(wv, pWvh, pWvl, D, D);
    k_trsp<<<dim3(DFF / 32, D / 32), 256>>>(w1, pW1h, pW1l, D, DFF);
    k_trsp<<<dim3(D / 32, DFF / 32), 256>>>(w2, pW2h, pW2l, DFF, D);

    // reduced Q,K path
    k_wsum<<<(D * H + 255) / 256, 256>>>(wq, wk);
    k_qskts<<<R, 256>>>(x);

    // V = X @ Wv  (tensor cores, 2-pass fp16)
    mma_gemm<0><<<dim3(D / 128, R / 128), 256, GEMM_SMEM>>>(
        pXh, pWvh, pWvl, nullptr, pYv, nullptr, R, D, D);

    // rel_w reductions -> A2, SA1, extremes
    k_relw<<<dim3(S / 2, BH), 256>>>(rel);
    k_finalize<<<BH, 256>>>();

    // one-hot softmax @ V
    k_attn2<<<dim3(S / 16, BH), 256>>>();

    // LN1 (+ fp16 h1)
    k_ln<1><<<R, 256>>>(x, pAttn, ln1g, ln1b, pH1, pH1h);

    // FFN GEMM1: mid = relu(h1 @ w1 + b1) -> fp16
    mma_gemm<1><<<dim3(DFF / 128, R / 128), 256, GEMM_SMEM>>>(
        pH1h, pW1h, pW1l, b1, nullptr, pMh, R, DFF, D);

    // FFN GEMM2: ffn = mid @ w2 + b2
    mma_gemm<2><<<dim3(D / 128, R / 128), 256, GEMM_SMEM>>>(
        pMh, pW2h, pW2l, b2, pFfn, nullptr, R, D, DFF);

    // LN2 -> output
    k_ln<0><<<R, 256>>>(pH1, pFfn, ln2g, ln2b, out, nullptr);
}

// round 7
// speedup vs baseline: 4.2362x; 1.3189x over previous
#include <cuda_runtime.h>
#include <cuda_fp16.h>
#include <math.h>
#include <float.h>
#include <stdint.h>

static constexpr int S = 1024;
static constexpr int Bd = 2;
static constexpr int D = 1024;
static constexpr int H = 16;
static constexpr int DEPTH = 64;
static constexpr int DFF = 4096;
static constexpr int R = S * Bd;      // 2048 token rows
static constexpr int BH = Bd * H;     // 32
static constexpr float SCALE = 0.125f;
static constexpr float NEGV = -1000000000.0f;
static constexpr float EPSV = 1e-5f;

// ------------------- scratch -------------------------------------------------
__device__ float g_Yv[R * D];
__device__ float g_attn[R * D];
__device__ float g_h1[R * D];
__device__ float g_ffn[R * D];
__device__ float g_wqsum[D * H];
__device__ float g_wksum[D * H];
__device__ float g_qsT[BH * S];
__device__ float g_ktsT[BH * S];
__device__ float g_A2[BH * S];
__device__ float g_P1[BH * S];
__device__ float g_SA1[BH];
__device__ float g_mx[BH];
__device__ float g_mn[BH];
__device__ float g_mx2[BH];
__device__ float g_mn2[BH];
__device__ int   g_kmx[BH];
__device__ int   g_kmn[BH];
// fp16 operands (single precision pass; error dominated by fp16 anyway)
__device__ __half g_Xh[R * D];
__device__ __half g_h1h[R * D];
__device__ __half g_midh[R * DFF];
__device__ __half g_WvT[D * D];
__device__ __half g_W1T[DFF * D];
__device__ __half g_W2T[D * DFF];

// ------------------- PTX helpers (baseline sm_80+ features only) -------------
__device__ __forceinline__ uint32_t smem_to_u32(const void* p) {
    uint32_t a;
    asm("{ .reg .u64 t; cvta.to.shared.u64 t, %1; cvt.u32.u64 %0, t; }" : "=r"(a) : "l"(p));
    return a;
}
__device__ __forceinline__ void ldsm4(uint32_t* r, uint32_t addr) {
    asm volatile("ldmatrix.sync.aligned.m8n8.x4.shared.b16 {%0,%1,%2,%3}, [%4];"
        : "=r"(r[0]), "=r"(r[1]), "=r"(r[2]), "=r"(r[3]) : "r"(addr));
}
__device__ __forceinline__ void mma16816(float* d, const uint32_t* a, const uint32_t* b) {
    asm volatile(
        "mma.sync.aligned.m16n8k16.row.col.f32.f16.f16.f32 "
        "{%0,%1,%2,%3}, {%4,%5,%6,%7}, {%8,%9}, {%0,%1,%2,%3};"
        : "+f"(d[0]), "+f"(d[1]), "+f"(d[2]), "+f"(d[3])
        : "r"(a[0]), "r"(a[1]), "r"(a[2]), "r"(a[3]), "r"(b[0]), "r"(b[1]));
}
__device__ __forceinline__ void cpasync16(uint32_t saddr, const void* gaddr) {
    asm volatile("cp.async.cg.shared.global [%0], [%1], 16;" :: "r"(saddr), "l"(gaddr));
}
#define CP_COMMIT() asm volatile("cp.async.commit_group;" ::: "memory")
#define CP_WAIT3()  asm volatile("cp.async.wait_group 3;" ::: "memory")
#define CP_WAIT2()  asm volatile("cp.async.wait_group 2;" ::: "memory")
#define CP_WAIT1()  asm volatile("cp.async.wait_group 1;" ::: "memory")
#define CP_WAIT0()  asm volatile("cp.async.wait_group 0;" ::: "memory")

// ------------------- K0: column-group sums of Wq, Wk -----------------------
__global__ void k_wsum(const float* __restrict__ wq, const float* __restrict__ wk) {
    int idx = blockIdx.x * blockDim.x + threadIdx.x;
    if (idx >= D * H) return;
    int k = idx / H, h = idx % H;
    const float* p1 = wq + (size_t)k * D + h * DEPTH;
    const float* p2 = wk + (size_t)k * D + h * DEPTH;
    float s1 = 0.f, s2 = 0.f;
#pragma unroll 16
    for (int d = 0; d < DEPTH; d++) { s1 += p1[d]; s2 += p2[d]; }
    g_wqsum[k * H + h] = s1;
    g_wksum[k * H + h] = s2;
}

// ------------------- K1: qs / kts -------------------------------------------
__global__ void k_qskts(const float* __restrict__ x) {
    int r = blockIdx.x;
    int t = threadIdx.x;
    int h = t & 15, part = t >> 4;
    float a1 = 0.f, a2 = 0.f;
    const float* xr = x + (size_t)r * D;
    for (int k = part; k < D; k += 16) {
        float xv = xr[k];
        a1 += xv * g_wqsum[k * H + h];
        a2 += xv * g_wksum[k * H + h];
    }
    __shared__ float s1[16][16];
    __shared__ float s2[16][16];
    s1[part][h] = a1; s2[part][h] = a2;
    __syncthreads();
    if (t < H) {
        float q = 0.f, kk = 0.f;
#pragma unroll
        for (int p = 0; p < 16; p++) { q += s1[p][t]; kk += s2[p][t]; }
        int b = r >> 10, s = r & 1023;
        g_qsT[(b * H + t) * S + s]  = SCALE * q;
        g_ktsT[(b * H + t) * S + s] = kk;
    }
}

// ------------------- cast X to fp16 -------------------------------------------
__global__ void k_split(const float* __restrict__ src, __half* __restrict__ dst, int n4) {
    int i = blockIdx.x * blockDim.x + threadIdx.x;
    if (i >= n4) return;
    float4 v = ((const float4*)src)[i];
    ((__half2*)dst)[i * 2]     = __floats2half2_rn(v.x, v.y);
    ((__half2*)dst)[i * 2 + 1] = __floats2half2_rn(v.z, v.w);
}

// ------------------- transpose: W[Kd][Nd] -> WT fp16 [Nd][Kd] -----------------
__global__ void k_trsp(const float* __restrict__ W, __half* __restrict__ T,
                       int Kd, int Nd) {
    __shared__ float tile[32][33];
    int n0 = blockIdx.x * 32, k0 = blockIdx.y * 32;
    int c = threadIdx.x & 31, rq = threadIdx.x >> 5;   // 256 threads
#pragma unroll
    for (int q = 0; q < 4; q++) {
        int kr = rq + q * 8;
        tile[kr][c] = W[(size_t)(k0 + kr) * Nd + n0 + c];
    }
    __syncthreads();
#pragma unroll
    for (int q = 0; q < 4; q++) {
        int nr = rq + q * 8;
        T[(size_t)(n0 + nr) * Kd + k0 + c] = __float2half_rn(tile[c][nr]);
    }
}

// ------------------- single-pass fp16 GEMM via mma.sync -----------------------
// C(M,N) = A(M,K) @ B(N,K)^T.
// EPI: 0 -> C fp32 ; 1 -> bias+relu -> Ch fp16 ; 2 -> bias -> C fp32
static constexpr int ROWB = 80;              // 32 fp16 (64B) + 16B pad
static constexpr int TILEB = 128 * ROWB;     // 10240
static constexpr int BUFB = 2 * TILEB;       // 20480 (A, B)
static constexpr int NSTAGE = 4;
static constexpr int GEMM_SMEM = NSTAGE * BUFB;   // 81920

template <int EPI>
__global__ void __launch_bounds__(256, 2)
mma_gemm(const __half* __restrict__ A, const __half* __restrict__ B,
         const float* __restrict__ bias, float* __restrict__ C,
         __half* __restrict__ Ch,
         int M, int N, int K) {
    extern __shared__ char smem[];
    const uint32_t sbase = smem_to_u32(smem);
    int t = threadIdx.x;
    int lane = t & 31, wid = t >> 5;
    int wm = wid >> 2, wn = wid & 3;           // 2 x 4 warp grid
    int m0 = blockIdx.y * 128, n0 = blockIdx.x * 128;

    // global->smem: thread t loads row lr, 32B half lh of each 64B tile row
    int lr = t >> 1, lh = t & 1;
    const __half* gsrc[2] = {
        A + (size_t)(m0 + lr) * K + lh * 16,
        B + (size_t)(n0 + lr) * K + lh * 16 };
    const uint32_t sdst = sbase + (uint32_t)(lr * ROWB + lh * 32);

    // ldmatrix lane address offsets
    uint32_t aoff = (uint32_t)((wm * 64 + ((lane >> 3) & 1) * 8 + (lane & 7)) * ROWB
                               + ((lane >> 4) & 1) * 16);
    uint32_t boff = (uint32_t)((wn * 32 + ((lane >> 4) & 1) * 8 + (lane & 7)) * ROWB
                               + ((lane >> 3) & 1) * 16);

    float acc[4][4][4];
#pragma unroll
    for (int i = 0; i < 4; i++)
#pragma unroll
        for (int j = 0; j < 4; j++)
#pragma unroll
            for (int e = 0; e < 4; e++) acc[i][j][e] = 0.f;

#define ISSUE(chunk, buf) do { \
    uint32_t _db = sdst + (uint32_t)(buf) * BUFB; \
    size_t _go = (size_t)(chunk) * 32; \
    _Pragma("unroll") \
    for (int _tl = 0; _tl < 2; _tl++) { \
        const __half* _g = gsrc[_tl] + _go; \
        cpasync16(_db + _tl * TILEB,      _g); \
        cpasync16(_db + _tl * TILEB + 16, _g + 8); \
    } } while (0)

    const int NC = K >> 5;
    ISSUE(0, 0); CP_COMMIT();
    ISSUE(1, 1); CP_COMMIT();
    ISSUE(2, 2); CP_COMMIT();

    int buf = 0;
    for (int c = 0; c < NC; c++) {
        if (c + 3 < NC) {
            int nb = buf + 3; if (nb >= NSTAGE) nb -= NSTAGE;
            ISSUE(c + 3, nb); CP_COMMIT(); CP_WAIT3();
        } else if (c + 2 < NC) {
            CP_WAIT2();
        } else if (c + 1 < NC) {
            CP_WAIT1();
        } else {
            CP_WAIT0();
        }
        __syncthreads();
        uint32_t bb = sbase + (uint32_t)buf * BUFB;
#pragma unroll
        for (int s = 0; s < 2; s++) {
            uint32_t Ah[4][4], Bh[2][4];
#pragma unroll
            for (int i = 0; i < 4; i++)
                ldsm4(Ah[i], bb + aoff + i * 16 * ROWB + s * 32);
#pragma unroll
            for (int j2 = 0; j2 < 2; j2++)
                ldsm4(Bh[j2], bb + TILEB + boff + j2 * 16 * ROWB + s * 32);
#pragma unroll
            for (int i = 0; i < 4; i++)
#pragma unroll
                for (int j = 0; j < 4; j++)
                    mma16816(acc[i][j], Ah[i], &Bh[j >> 1][(j & 1) * 2]);
        }
        __syncthreads();
        if (++buf == NSTAGE) buf = 0;
    }
#undef ISSUE

    // epilogue
    int r0 = lane >> 2, c2 = (lane & 3) * 2;
#pragma unroll
    for (int i = 0; i < 4; i++) {
#pragma unroll
        for (int j = 0; j < 4; j++) {
            int m = m0 + wm * 64 + i * 16 + r0;
            int n = n0 + wn * 32 + j * 8 + c2;
            float v0 = acc[i][j][0], v1 = acc[i][j][1];
            float v2 = acc[i][j][2], v3 = acc[i][j][3];
            if constexpr (EPI >= 1) {
                float b0 = bias[n], b1 = bias[n + 1];
                v0 += b0; v1 += b1; v2 += b0; v3 += b1;
            }
            if constexpr (EPI == 1) {
                v0 = fmaxf(v0, 0.f); v1 = fmaxf(v1, 0.f);
                v2 = fmaxf(v2, 0.f); v3 = fmaxf(v3, 0.f);
                *(__half2*)(Ch + (size_t)m * N + n)       = __floats2half2_rn(v0, v1);
                *(__half2*)(Ch + (size_t)(m + 8) * N + n) = __floats2half2_rn(v2, v3);
            } else {
                *(float2*)(C + (size_t)m * N + n)       = make_float2(v0, v1);
                *(float2*)(C + (size_t)(m + 8) * N + n) = make_float2(v2, v3);
            }
        }
    }
}

// ------------------- K3: rel_w weighted reductions (balanced pairs) ----------
__global__ void k_relw(const float* __restrict__ rel) {
    int p = blockIdx.x;       // 0..511
    int bh = blockIdx.y;      // 0..31
    int t = threadIdx.x;      // 256
    int k1 = p, k2 = 1023 - p;
    const float* kts = g_ktsT + bh * S;
    const float* r1 = rel + ((size_t)bh * S + k1) * S + (1023 - k1);
    const float* r2 = rel + ((size_t)bh * S + k2) * S + (1023 - k2);
    float s11 = 0.f, s12 = 0.f, s21 = 0.f, s22 = 0.f;
    for (int m = t; m <= k1; m += 256) {
        float rv = r1[m], kv = kts[m];
        s11 += kv * rv;
        s12 += (kv + NEGV * (float)min(m, 64)) * rv;
    }
    for (int m = t; m <= k2; m += 256) {
        float rv = r2[m], kv = kts[m];
        s21 += kv * rv;
        s22 += (kv + NEGV * (float)min(m, 64)) * rv;
    }
    __shared__ float4 red[256];
    red[t] = make_float4(s11, s12, s21, s22);
    __syncthreads();
    for (int o = 128; o > 0; o >>= 1) {
        if (t < o) {
            float4 a = red[t], b = red[t + o];
            red[t] = make_float4(a.x + b.x, a.y + b.y, a.z + b.z, a.w + b.w);
        }
        __syncthreads();
    }
    if (t == 0) {
        float4 v = red[0];
        g_P1[bh * S + k1] = v.x;
        g_A2[bh * S + k1] = v.y;
        g_P1[bh * S + k2] = v.z;
        g_A2[bh * S + k2] = v.w;
    }
}

// ------------------- K4: SA1 + top-2 extremes per bh -------------------------
__global__ void k_finalize() {
    int bh = blockIdx.x, t = threadIdx.x;
    __shared__ float ss[256];
    __shared__ float sv[256];
    __shared__ int   si[256];
    __shared__ float sw_[256];
    __shared__ int   sj[256];
    const float* A2 = g_A2 + bh * S;
    float sa = 0.f, mx = -FLT_MAX, mn = FLT_MAX;
    int im = 0, imn = 0;
    for (int k = t; k < S; k += 256) {
        sa += g_P1[bh * S + k];
        float a = A2[k];
        if (a > mx) { mx = a; im = k; }
        if (a < mn) { mn = a; imn = k; }
    }
    ss[t] = sa; sv[t] = mx; si[t] = im; sw_[t] = mn; sj[t] = imn;
    __syncthreads();
    for (int o = 128; o > 0; o >>= 1) {
        if (t < o) {
            ss[t] += ss[t + o];
            if (sv[t + o] > sv[t]) { sv[t] = sv[t + o]; si[t] = si[t + o]; }
            if (sw_[t + o] < sw_[t]) { sw_[t] = sw_[t + o]; sj[t] = sj[t + o]; }
        }
        __syncthreads();
    }
    int kmx = si[0], kmn = sj[0];
    float vmx = sv[0], vmn = sw_[0], vsa = ss[0];
    __syncthreads();
    float mx2 = -FLT_MAX, mn2 = FLT_MAX;
    for (int k = t; k < S; k += 256) {
        float a = A2[k];
        if (k != kmx && a > mx2) mx2 = a;
        if (k != kmn && a < mn2) mn2 = a;
    }
    sv[t] = mx2; sw_[t] = mn2;
    __syncthreads();
    for (int o = 128; o > 0; o >>= 1) {
        if (t < o) { sv[t] = fmaxf(sv[t], sv[t + o]); sw_[t] = fminf(sw_[t], sw_[t + o]); }
        __syncthreads();
    }
    if (t == 0) {
        g_SA1[bh] = vsa;
        g_mx[bh] = vmx; g_mn[bh] = vmn;
        g_mx2[bh] = sv[0]; g_mn2[bh] = sw_[0];
        g_kmx[bh] = kmx; g_kmn[bh] = kmn;
    }
}

// ------------------- K5: one-hot gather + exact fallback ---------------------
__global__ void __launch_bounds__(256) k_attn2() {
    int bh = blockIdx.y;
    int b = bh >> 4, h = bh & 15;
    int t = threadIdx.x;
    int rg = t >> 4;
    int lane = t & 15;
    int j = blockIdx.x * 16 + rg;

    float cj = SCALE * g_qsT[bh * S + j] * g_SA1[bh];
    const float* Vb = g_Yv + (size_t)b * S * D + h * DEPTH;
    float* outp = g_attn + ((size_t)bh * S + j) * DEPTH;

    bool fast = false; int kwin = 0;
    if (cj > 0.f)      { fast = cj * (g_mx[bh] - g_mx2[bh]) > 90.f;  kwin = g_kmx[bh]; }
    else if (cj < 0.f) { fast = (-cj) * (g_mn2[bh] - g_mn[bh]) > 90.f; kwin = g_kmn[bh]; }

    if (fast) {
        float4 v = *(const float4*)(Vb + (size_t)kwin * D + lane * 4);
        *(float4*)(outp + lane * 4) = v;
    } else {
        float mj = (cj >= 0.f) ? cj * g_mx[bh] : cj * g_mn[bh];
        const float* A2 = g_A2 + bh * S;
        float den = 0.f;
        float4 acc = make_float4(0.f, 0.f, 0.f, 0.f);
        for (int k = 0; k < S; k++) {
            float e = __expf(fminf(cj * A2[k] - mj, 0.f));
            den += e;
            float4 v = *(const float4*)(Vb + (size_t)k * D + lane * 4);
            acc.x = fmaf(e, v.x, acc.x);
            acc.y = fmaf(e, v.y, acc.y);
            acc.z = fmaf(e, v.z, acc.z);
            acc.w = fmaf(e, v.w, acc.w);
        }
        float inv = 1.f / den;
        acc.x *= inv; acc.y *= inv; acc.z *= inv; acc.w *= inv;
        *(float4*)(outp + lane * 4) = acc;
    }
}

// ------------------- LN(a + b) [optionally emit fp16] ------------------------
template <int SPLIT>
__global__ void k_ln(const float* __restrict__ xa, const float* __restrict__ xb,
                     const float* __restrict__ gam, const float* __restrict__ bet,
                     float* __restrict__ out, __half* __restrict__ oh) {
    int r = blockIdx.x, t = threadIdx.x;
    const float* pa = xa + (size_t)r * D;
    const float* pb = xb + (size_t)r * D;
    float v[4];
    float s = 0.f;
#pragma unroll
    for (int i = 0; i < 4; i++) {
        int c = t + i * 256;
        v[i] = pa[c] + pb[c];
        s += v[i];
    }
    __shared__ float red[256];
    red[t] = s; __syncthreads();
    for (int o = 128; o > 0; o >>= 1) {
        if (t < o) red[t] += red[t + o];
        __syncthreads();
    }
    float mu = red[0] * (1.f / 1024.f);
    __syncthreads();
    float s2 = 0.f;
#pragma unroll
    for (int i = 0; i < 4; i++) { float dd = v[i] - mu; s2 += dd * dd; }
    red[t] = s2; __syncthreads();
    for (int o = 128; o > 0; o >>= 1) {
        if (t < o) red[t] += red[t + o];
        __syncthreads();
    }
    float inv = rsqrtf(red[0] * (1.f / 1024.f) + EPSV);
    float* po = out + (size_t)r * D;
#pragma unroll
    for (int i = 0; i < 4; i++) {
        int c = t + i * 256;
        float y = (v[i] - mu) * inv * gam[c] + bet[c];
        po[c] = y;
        if constexpr (SPLIT) oh[(size_t)r * D + c] = __float2half_rn(y);
    }
}

// ------------------- launch ---------------------------------------------------
extern "C" void kernel_launch(void* const* d_in, const int* in_sizes, int n_in,
                              void* d_out, int out_size) {
    const float* x    = (const float*)d_in[0];
    const float* wq   = (const float*)d_in[1];
    const float* wk   = (const float*)d_in[2];
    const float* wv   = (const float*)d_in[3];
    const float* rel  = (const float*)d_in[4];
    const float* w1   = (const float*)d_in[5];
    const float* b1   = (const float*)d_in[6];
    const float* w2   = (const float*)d_in[7];
    const float* b2   = (const float*)d_in[8];
    const float* ln1g = (const float*)d_in[9];
    const float* ln1b = (const float*)d_in[10];
    const float* ln2g = (const float*)d_in[11];
    const float* ln2b = (const float*)d_in[12];
    float* out = (float*)d_out;

    cudaFuncSetAttribute(mma_gemm<0>, cudaFuncAttributeMaxDynamicSharedMemorySize, GEMM_SMEM);
    cudaFuncSetAttribute(mma_gemm<1>, cudaFuncAttributeMaxDynamicSharedMemorySize, GEMM_SMEM);
    cudaFuncSetAttribute(mma_gemm<2>, cudaFuncAttributeMaxDynamicSharedMemorySize, GEMM_SMEM);

    float *pYv, *pAttn, *pH1, *pFfn;
    __half *pXh, *pH1h, *pMh, *pWv, *pW1, *pW2;
    cudaGetSymbolAddress((void**)&pYv,   g_Yv);
    cudaGetSymbolAddress((void**)&pAttn, g_attn);
    cudaGetSymbolAddress((void**)&pH1,   g_h1);
    cudaGetSymbolAddress((void**)&pFfn,  g_ffn);
    cudaGetSymbolAddress((void**)&pXh,   g_Xh);
    cudaGetSymbolAddress((void**)&pH1h,  g_h1h);
    cudaGetSymbolAddress((void**)&pMh,   g_midh);
    cudaGetSymbolAddress((void**)&pWv,   g_WvT);
    cudaGetSymbolAddress((void**)&pW1,   g_W1T);
    cudaGetSymbolAddress((void**)&pW2,   g_W2T);

    // prep: cast + weight transposes
    k_split<<<(R * D / 4 + 255) / 256, 256>>>(x, pXh, R * D / 4);
    k_trsp<<<dim3(D / 32, D / 32), 256>>>(wv, pWv, D, D);
    k_trsp<<<dim3(DFF / 32, D / 32), 256>>>(w1, pW1, D, DFF);
    k_trsp<<<dim3(D / 32, DFF / 32), 256>>>(w2, pW2, DFF, D);

    // reduced Q,K path
    k_wsum<<<(D * H + 255) / 256, 256>>>(wq, wk);
    k_qskts<<<R, 256>>>(x);

    // V = X @ Wv
    mma_gemm<0><<<dim3(D / 128, R / 128), 256, GEMM_SMEM>>>(
        pXh, pWv, nullptr, pYv, nullptr, R, D, D);

    // rel_w reductions -> A2, SA1, extremes
    k_relw<<<dim3(S / 2, BH), 256>>>(rel);
    k_finalize<<<BH, 256>>>();

    // one-hot softmax @ V
    k_attn2<<<dim3(S / 16, BH), 256>>>();

    // LN1 (+ fp16 h1)
    k_ln<1><<<R, 256>>>(x, pAttn, ln1g, ln1b, pH1, pH1h);

    // FFN GEMM1: mid = relu(h1 @ w1 + b1) -> fp16
    mma_gemm<1><<<dim3(DFF / 128, R / 128), 256, GEMM_SMEM>>>(
        pH1h, pW1, b1, nullptr, pMh, R, DFF, D);

    // FFN GEMM2: ffn = mid @ w2 + b2
    mma_gemm<2><<<dim3(D / 128, R / 128), 256, GEMM_SMEM>>>(
        pMh, pW2, b2, pFfn, nullptr, R, D, DFF);

    // LN2 -> output
    k_ln<0><<<R, 256>>>(pH1, pFfn, ln2g, ln2b, out, nullptr);
}